// round 1
// baseline (speedup 1.0000x reference)
#include <cuda_runtime.h>
#include <cstdint>

#define TSEQ 2048
#define NB   4
#define NH   8
#define DKK  64
#define DVV  128
#define HIDD 1024
#define MROWS (NB*TSEQ)   // 8192

// ---------------- scratch (device globals; no allocations allowed) ----------
__device__ float g_Q [MROWS*512];
__device__ float g_K [MROWS*512];
__device__ float g_V [MROWS*1024];
__device__ float g_Qc[MROWS*512];
__device__ float g_Kc[MROWS*512];
__device__ float g_Vc[MROWS*1024];
__device__ float g_A [MROWS*1024];
__device__ float g_G [MROWS*1024];
__device__ float g_Bt[MROWS*8];
__device__ float g_O [MROWS*1024];

// ---------------- generic C = X @ W^T (+bias)(+sigmoid) ---------------------
// X: (M,K) row-major, W: (N,K) row-major, C: (M,N) row-major.
// 128x128 tile, BK=8, 256 threads, 8x8 microtile, prefetched gmem tile.
__global__ __launch_bounds__(256) void gemm_xwt(
    const float* __restrict__ A, const float* __restrict__ W,
    const float* __restrict__ bias, float* __restrict__ C,
    int N, int Kd, int act)
{
    __shared__ float As[8][128];
    __shared__ float Bs[8][128];
    const int tid = threadIdx.x;
    const int m0 = blockIdx.y * 128;
    const int n0 = blockIdx.x * 128;
    const int lr = tid >> 1;          // 0..127
    const int lk = (tid & 1) * 4;     // 0 or 4
    const float* Ap = A + (size_t)(m0 + lr) * Kd + lk;
    const float* Wp = W + (size_t)(n0 + lr) * Kd + lk;
    const int tr = (tid >> 4) * 8;    // 0..120
    const int tc = (tid & 15) * 8;    // 0..120

    float acc[8][8];
#pragma unroll
    for (int i = 0; i < 8; i++)
#pragma unroll
        for (int j = 0; j < 8; j++) acc[i][j] = 0.f;

    float4 av = *(const float4*)Ap;
    float4 wv = *(const float4*)Wp;

    for (int k0 = 0; k0 < Kd; k0 += 8) {
        __syncthreads();
        As[lk+0][lr]=av.x; As[lk+1][lr]=av.y; As[lk+2][lr]=av.z; As[lk+3][lr]=av.w;
        Bs[lk+0][lr]=wv.x; Bs[lk+1][lr]=wv.y; Bs[lk+2][lr]=wv.z; Bs[lk+3][lr]=wv.w;
        __syncthreads();
        if (k0 + 8 < Kd) {
            av = *(const float4*)(Ap + k0 + 8);
            wv = *(const float4*)(Wp + k0 + 8);
        }
#pragma unroll
        for (int kk = 0; kk < 8; kk++) {
            float am[8], bn[8];
            *(float4*)&am[0] = *(const float4*)&As[kk][tr];
            *(float4*)&am[4] = *(const float4*)&As[kk][tr+4];
            *(float4*)&bn[0] = *(const float4*)&Bs[kk][tc];
            *(float4*)&bn[4] = *(const float4*)&Bs[kk][tc+4];
#pragma unroll
            for (int i = 0; i < 8; i++)
#pragma unroll
                for (int j = 0; j < 8; j++)
                    acc[i][j] = fmaf(am[i], bn[j], acc[i][j]);
        }
    }

#pragma unroll
    for (int i = 0; i < 8; i++) {
        float* crow = C + (size_t)(m0 + tr + i) * N + n0 + tc;
        float outv[8];
#pragma unroll
        for (int j = 0; j < 8; j++) {
            float v = acc[i][j];
            if (bias) v += bias[n0 + tc + j];
            if (act)  v = 1.f / (1.f + __expf(-v));
            outv[j] = v;
        }
        *(float4*)(crow + 0) = *(float4*)&outv[0];
        *(float4*)(crow + 4) = *(float4*)&outv[4];
    }
}

// ---------------- beta = sigmoid(x @ Wb^T + bb), Wb: (8,1024) ---------------
__global__ __launch_bounds__(256) void beta_proj(
    const float* __restrict__ x, const float* __restrict__ Wb,
    const float* __restrict__ bb, float* __restrict__ Bt)
{
    const int m = blockIdx.x;
    const int w = threadIdx.x >> 5;    // head 0..7
    const int lane = threadIdx.x & 31;
    const float* xr = x  + (size_t)m * HIDD;
    const float* wr = Wb + (size_t)w * HIDD;
    float s = 0.f;
#pragma unroll
    for (int k = lane * 4; k < HIDD; k += 128) {
        float4 xv = *(const float4*)(xr + k);
        float4 wv = *(const float4*)(wr + k);
        s += xv.x*wv.x + xv.y*wv.y + xv.z*wv.z + xv.w*wv.w;
    }
#pragma unroll
    for (int o = 16; o; o >>= 1) s += __shfl_xor_sync(0xffffffffu, s, o);
    if (lane == 0) Bt[m*8 + w] = 1.f / (1.f + __expf(-(s + bb[w])));
}

// ---------------- depthwise causal conv (K=4) + silu (+scale) ---------------
__global__ __launch_bounds__(256) void conv_silu(
    const float* __restrict__ in, const float* __restrict__ w,
    const float* __restrict__ bias, float* __restrict__ outp,
    int C, float scale)
{
    const int idx = blockIdx.x * blockDim.x + threadIdx.x;
    if (idx >= MROWS * C) return;
    const int c = idx % C;
    const int m = idx / C;          // m = b*T + t
    const int t = m & (TSEQ - 1);
    const float* wc = w + c * 4;
    float acc = bias[c];
#pragma unroll
    for (int j = 0; j < 4; j++) {
        const int tt = t - 3 + j;
        if (tt >= 0) acc = fmaf(wc[j], in[(size_t)(m - 3 + j) * C + c], acc);
    }
    const float s = acc * (1.f / (1.f + __expf(-acc)));
    outp[(size_t)m * C + c] = s * scale;
}

// ---------------- gated delta-rule recurrence -------------------------------
// Per (b,h,v-column): s <- a[v]*s - beta*(k . s - v[v])*k ;  o[v] = q . s
// grid (B*H, DV/32), block 64: 2 threads per column (32 S regs each).
__global__ __launch_bounds__(64) void delta_recurrence(
    const float* __restrict__ Qc, const float* __restrict__ Kc,
    const float* __restrict__ Vc, const float* __restrict__ Ag,
    const float* __restrict__ Bt, float* __restrict__ O)
{
    const int bh = blockIdx.x;
    const int b = bh >> 3, h = bh & 7;
    const int tid = threadIdx.x;
    const int w   = tid >> 5;
    const int lane = tid & 31;
    const int hlf = tid & 1;                 // which DK half
    const int vcol = blockIdx.y * 32 + (tid >> 1);

    __shared__ float sk[2][2][68];           // [warp][buf][padded 64]
    __shared__ float sq[2][2][68];

    float S[32];
#pragma unroll
    for (int i = 0; i < 32; i++) S[i] = 0.f;

    const float* kb = Kc + (size_t)b * TSEQ * 512  + h * 64;
    const float* qb = Qc + (size_t)b * TSEQ * 512  + h * 64;
    const float* vb = Vc + (size_t)b * TSEQ * 1024 + h * 128 + vcol;
    const float* ab = Ag + (size_t)b * TSEQ * 1024 + h * 128 + vcol;
    const float* bbp = Bt + (size_t)b * TSEQ * 8   + h;
    float*       ob = O  + (size_t)b * TSEQ * 1024 + h * 128 + vcol;

    const int e  = 2 * lane;                 // element pair this lane stages
    const int p0 = e + (e >> 5);             // padded position (+1 for hi half)
    const int kpad = hlf * 33;               // padded base of this thread's DK half

    // prologue load (t = 0)
    float2 kn = *(const float2*)(kb + e);
    float2 qn = *(const float2*)(qb + e);
    float a_n = ab[0], v_n = vb[0], be_n = bbp[0];

    int buf = 1;
    for (int t = 0; t < TSEQ; t++) {
        buf ^= 1;
        sk[w][buf][p0]   = kn.x; sk[w][buf][p0+1] = kn.y;
        sq[w][buf][p0]   = qn.x; sq[w][buf][p0+1] = qn.y;
        const float a_c = a_n, v_c = v_n, be_c = be_n;
        __syncwarp();
        if (t + 1 < TSEQ) {                  // prefetch next step
            const size_t r = (size_t)(t + 1);
            kn = *(const float2*)(kb + r * 512 + e);
            qn = *(const float2*)(qb + r * 512 + e);
            a_n = ab[r * 1024]; v_n = vb[r * 1024]; be_n = bbp[r * 8];
        }
        const float* skc = &sk[w][buf][kpad];
        const float* sqc = &sq[w][buf][kpad];

        float r0 = 0.f, r1 = 0.f;
#pragma unroll
        for (int j = 0; j < 32; j += 2) {
            r0 = fmaf(skc[j],   S[j],   r0);
            r1 = fmaf(skc[j+1], S[j+1], r1);
        }
        float rd = r0 + r1;
        rd += __shfl_xor_sync(0xffffffffu, rd, 1);
        const float cc = be_c * (rd - v_c);

        float o0 = 0.f, o1 = 0.f;
#pragma unroll
        for (int j = 0; j < 32; j += 2) {
            const float k0v = skc[j], k1v = skc[j+1];
            S[j]   = fmaf(a_c, S[j],   -cc * k0v);
            S[j+1] = fmaf(a_c, S[j+1], -cc * k1v);
            o0 = fmaf(sqc[j],   S[j],   o0);
            o1 = fmaf(sqc[j+1], S[j+1], o1);
        }
        float oo = o0 + o1;
        oo += __shfl_xor_sync(0xffffffffu, oo, 1);
        if (hlf == 0) ob[(size_t)t * 1024] = oo;
    }
}

// ---------------- LayerNorm over DV + sigmoid-gate multiply (in place) ------
__global__ __launch_bounds__(256) void ln_gate(
    float* __restrict__ O, const float* __restrict__ G,
    const float* __restrict__ lnw, const float* __restrict__ lnb)
{
    const int g = blockIdx.x * 8 + (threadIdx.x >> 5);   // group = (m,h)
    const int lane = threadIdx.x & 31;
    const int m = g >> 3, h = g & 7;
    float* row = O + (size_t)m * 1024 + h * 128;
    const float* grow = G + (size_t)m * 1024 + h * 128;

    float xs[4];
    float sum = 0.f;
#pragma unroll
    for (int i = 0; i < 4; i++) { xs[i] = row[lane + 32*i]; sum += xs[i]; }
#pragma unroll
    for (int o = 16; o; o >>= 1) sum += __shfl_xor_sync(0xffffffffu, sum, o);
    const float mu = sum * (1.f / 128.f);

    float vs = 0.f;
#pragma unroll
    for (int i = 0; i < 4; i++) { const float d = xs[i] - mu; vs = fmaf(d, d, vs); }
#pragma unroll
    for (int o = 16; o; o >>= 1) vs += __shfl_xor_sync(0xffffffffu, vs, o);
    const float rstd = rsqrtf(vs * (1.f / 128.f) + 1e-5f);

#pragma unroll
    for (int i = 0; i < 4; i++) {
        const int c = lane + 32*i;
        row[c] = ((xs[i] - mu) * rstd * lnw[c] + lnb[c]) * grow[c];
    }
}

// ---------------- launch ----------------------------------------------------
extern "C" void kernel_launch(void* const* d_in, const int* in_sizes, int n_in,
                              void* d_out, int out_size)
{
    const float* x   = (const float*)d_in[0];
    const float* Wq  = (const float*)d_in[1];
    const float* Wk  = (const float*)d_in[2];
    const float* Wv  = (const float*)d_in[3];
    const float* Wa  = (const float*)d_in[4];
    const float* ba  = (const float*)d_in[5];
    const float* Wb  = (const float*)d_in[6];
    const float* bbv = (const float*)d_in[7];
    const float* Wg  = (const float*)d_in[8];
    const float* Wo  = (const float*)d_in[9];
    const float* qcw = (const float*)d_in[10];
    const float* qcb = (const float*)d_in[11];
    const float* kcw = (const float*)d_in[12];
    const float* kcb = (const float*)d_in[13];
    const float* vcw = (const float*)d_in[14];
    const float* vcb = (const float*)d_in[15];
    const float* lnw = (const float*)d_in[16];
    const float* lnb = (const float*)d_in[17];
    float* outp = (float*)d_out;

    float *Q, *K, *V, *Qc, *Kc, *Vc, *A, *G, *Bt, *O;
    cudaGetSymbolAddress((void**)&Q,  g_Q);
    cudaGetSymbolAddress((void**)&K,  g_K);
    cudaGetSymbolAddress((void**)&V,  g_V);
    cudaGetSymbolAddress((void**)&Qc, g_Qc);
    cudaGetSymbolAddress((void**)&Kc, g_Kc);
    cudaGetSymbolAddress((void**)&Vc, g_Vc);
    cudaGetSymbolAddress((void**)&A,  g_A);
    cudaGetSymbolAddress((void**)&G,  g_G);
    cudaGetSymbolAddress((void**)&Bt, g_Bt);
    cudaGetSymbolAddress((void**)&O,  g_O);

    // input projections
    gemm_xwt<<<dim3(4, 64), 256>>>(x, Wq, nullptr, Q, 512, HIDD, 0);
    gemm_xwt<<<dim3(4, 64), 256>>>(x, Wk, nullptr, K, 512, HIDD, 0);
    gemm_xwt<<<dim3(8, 64), 256>>>(x, Wv, nullptr, V, 1024, HIDD, 0);
    gemm_xwt<<<dim3(8, 64), 256>>>(x, Wa, ba,      A, 1024, HIDD, 1);
    gemm_xwt<<<dim3(8, 64), 256>>>(x, Wg, nullptr, G, 1024, HIDD, 1);
    beta_proj<<<MROWS, 256>>>(x, Wb, bbv, Bt);

    // depthwise causal conv + silu (k gets the DK^-0.5 scale fused)
    conv_silu<<<(MROWS*512 +255)/256, 256>>>(Q, qcw, qcb, Qc,  512, 1.f);
    conv_silu<<<(MROWS*512 +255)/256, 256>>>(K, kcw, kcb, Kc,  512, 0.125f);
    conv_silu<<<(MROWS*1024+255)/256, 256>>>(V, vcw, vcb, Vc, 1024, 1.f);

    // sequential gated delta-rule scan
    delta_recurrence<<<dim3(NB*NH, 4), 64>>>(Qc, Kc, Vc, A, Bt, O);

    // LN + gate, then output projection
    ln_gate<<<MROWS, 256>>>(O, G, lnw, lnb);
    gemm_xwt<<<dim3(8, 64), 256>>>(O, Wo, nullptr, outp, 1024, HIDD, 0);
}

// round 3
// speedup vs baseline: 1.4631x; 1.4631x over previous
#include <cuda_runtime.h>
#include <cuda_bf16.h>
#include <cstdint>

#define TSEQ 2048
#define NB   4
#define NH   8
#define HIDD 1024
#define MROWS (NB*TSEQ)   // 8192

// ---------------- scratch (device globals; no allocations allowed) ----------
__device__ float g_Q [MROWS*512];
__device__ float g_K [MROWS*512];
__device__ float g_V [MROWS*1024];
__device__ float g_Qc[MROWS*512];
__device__ float g_Kc[MROWS*512];
__device__ float g_Vc[MROWS*1024];
__device__ float g_A [MROWS*1024];
__device__ float g_G [MROWS*1024];
__device__ float g_Bt[MROWS*8];
__device__ float g_O [MROWS*1024];

// bf16 split buffers
__device__ __nv_bfloat16 g_Xhi[MROWS*1024];
__device__ __nv_bfloat16 g_Xlo[MROWS*1024];
__device__ __nv_bfloat16 g_Ohi[MROWS*1024];
__device__ __nv_bfloat16 g_Olo[MROWS*1024];
// all weights hi/lo concatenated: q(512K) k(512K) v(1M) a(1M) g(1M) o(1M)
#define WOFF_Q 0
#define WOFF_K 524288
#define WOFF_V 1048576
#define WOFF_A 2097152
#define WOFF_G 3145728
#define WOFF_O 4194304
__device__ __nv_bfloat16 g_Whi[5242880];
__device__ __nv_bfloat16 g_Wlo[5242880];

// ---------------- PTX helpers (sm_80-class only; compute_103-safe) ----------
static __device__ __forceinline__ uint32_t smem_u32(const void* p) {
    uint32_t a;
    asm("{ .reg .u64 t; cvta.to.shared.u64 t, %1; cvt.u32.u64 %0, t; }"
        : "=r"(a) : "l"(p));
    return a;
}

#define LDSM4(r, a)                                                             \
    asm volatile("ldmatrix.sync.aligned.m8n8.x4.shared.b16 {%0,%1,%2,%3}, [%4];"\
        : "=r"((r)[0]), "=r"((r)[1]), "=r"((r)[2]), "=r"((r)[3]) : "r"(a))

#define MMA16816(d, a, b0, b1)                                                  \
    asm volatile(                                                               \
        "mma.sync.aligned.m16n8k16.row.col.f32.bf16.bf16.f32 "                  \
        "{%0,%1,%2,%3},{%4,%5,%6,%7},{%8,%9},{%0,%1,%2,%3};"                    \
        : "+f"((d)[0]), "+f"((d)[1]), "+f"((d)[2]), "+f"((d)[3])                \
        : "r"((a)[0]), "r"((a)[1]), "r"((a)[2]), "r"((a)[3]), "r"(b0), "r"(b1))

#define CPA16(dst, src)                                                         \
    asm volatile("cp.async.cg.shared.global [%0], [%1], 16;"                    \
        :: "r"(dst), "l"(src) : "memory")

// ---------------- fp32 -> bf16 hi/lo split -----------------------------------
__global__ __launch_bounds__(256) void split_bf16(
    const float* __restrict__ in, __nv_bfloat16* __restrict__ hi,
    __nv_bfloat16* __restrict__ lo, int n4)
{
    const int i = blockIdx.x * 256 + threadIdx.x;
    if (i >= n4) return;
    const float4 v = ((const float4*)in)[i];
    __nv_bfloat16 h0 = __float2bfloat16(v.x);
    __nv_bfloat16 h1 = __float2bfloat16(v.y);
    __nv_bfloat16 h2 = __float2bfloat16(v.z);
    __nv_bfloat16 h3 = __float2bfloat16(v.w);
    __nv_bfloat16 l0 = __float2bfloat16(v.x - __bfloat162float(h0));
    __nv_bfloat16 l1 = __float2bfloat16(v.y - __bfloat162float(h1));
    __nv_bfloat16 l2 = __float2bfloat16(v.z - __bfloat162float(h2));
    __nv_bfloat16 l3 = __float2bfloat16(v.w - __bfloat162float(h3));
    __nv_bfloat162 H0; H0.x = h0; H0.y = h1;
    __nv_bfloat162 H1; H1.x = h2; H1.y = h3;
    __nv_bfloat162 L0; L0.x = l0; L0.y = l1;
    __nv_bfloat162 L1; L1.x = l2; L1.y = l3;
    ((__nv_bfloat162*)hi)[2*i]   = H0;
    ((__nv_bfloat162*)hi)[2*i+1] = H1;
    ((__nv_bfloat162*)lo)[2*i]   = L0;
    ((__nv_bfloat162*)lo)[2*i+1] = L1;
}

// ---------------- HMMA GEMM: C = A @ B^T (fp32 via bf16 3-pass) -------------
// A: (M,1024) bf16 hi/lo row-major; B: (Nt,1024) bf16 hi/lo row-major;
// C: (M,Nt) fp32 row-major. 128x128 tile, BK=32, cp.async double buffer.
// smem per buffer: 4 tiles (Ah,Al,Bh,Bl) of 128 rows x 80B pitch = 40960B.
#define GSMEM 81920

__global__ __launch_bounds__(256) void gemm_hmma(
    const __nv_bfloat16* __restrict__ Ahi, const __nv_bfloat16* __restrict__ Alo,
    const __nv_bfloat16* __restrict__ Bhi, const __nv_bfloat16* __restrict__ Blo,
    const float* __restrict__ bias, float* __restrict__ C, int Nt, int act)
{
    extern __shared__ char smc[];
    const uint32_t sb = smem_u32(smc);
    const int tid = threadIdx.x;
    const int l   = tid & 31, wid = tid >> 5;
    const int wm  = wid & 1, wn = wid >> 1;      // warp grid 2 (m) x 4 (n)
    const int m0  = blockIdx.y << 7, n0 = blockIdx.x << 7;
    const int grp = l >> 3;

    // ldmatrix per-thread address offsets (bytes), pitch = 80B
    const uint32_t a_off = (uint32_t)((wm*64 + (grp & 1)*8 + (l & 7)) * 80
                                      + (grp >> 1) * 16);
    const uint32_t b_off = (uint32_t)((wn*32 + (grp >> 1)*8 + (l & 7)) * 80
                                      + (grp & 1) * 16);

    const __nv_bfloat16* s0 = Ahi + (size_t)m0 * 1024;
    const __nv_bfloat16* s1 = Alo + (size_t)m0 * 1024;
    const __nv_bfloat16* s2 = Bhi + (size_t)n0 * 1024;
    const __nv_bfloat16* s3 = Blo + (size_t)n0 * 1024;

    float acc[4][4][4];
#pragma unroll
    for (int mt = 0; mt < 4; mt++)
#pragma unroll
        for (int nt = 0; nt < 4; nt++)
#pragma unroll
            for (int r = 0; r < 4; r++) acc[mt][nt][r] = 0.f;

    const int crow = 0;  (void)crow;

#define LOAD_BUF(buf, k0) do {                                                  \
    const uint32_t bb_ = sb + (uint32_t)(buf) * 40960u;                         \
    const __nv_bfloat16* ss_[4] = { s0, s1, s2, s3 };                           \
    _Pragma("unroll")                                                           \
    for (int t4 = 0; t4 < 4; t4++) {                                            \
        _Pragma("unroll")                                                       \
        for (int it = 0; it < 2; it++) {                                        \
            const int idx_ = it * 256 + tid;                                    \
            const int row_ = idx_ >> 2, ch_ = idx_ & 3;                         \
            const uint32_t dst_ = bb_ + t4 * 10240u + row_ * 80u + ch_ * 16u;   \
            const __nv_bfloat16* src_ = ss_[t4] + (size_t)row_ * 1024 + (k0) + ch_ * 8; \
            CPA16(dst_, src_);                                                  \
        }                                                                       \
    }                                                                           \
    asm volatile("cp.async.commit_group;" ::: "memory");                        \
} while (0)

    LOAD_BUF(0, 0);

    for (int c = 0; c < 32; c++) {
        asm volatile("cp.async.wait_group 0;" ::: "memory");
        __syncthreads();
        if (c + 1 < 32) LOAD_BUF((c + 1) & 1, (c + 1) * 32);
        const uint32_t bb = sb + (uint32_t)(c & 1) * 40960u;
#pragma unroll
        for (int ks = 0; ks < 2; ks++) {
            const uint32_t ko = (uint32_t)ks * 32u;
            uint32_t ah[16], al[16], bh[8], bl[8];
#pragma unroll
            for (int mt = 0; mt < 4; mt++)
                LDSM4(ah + 4*mt, bb + a_off + mt * 1280u + ko);
#pragma unroll
            for (int np = 0; np < 2; np++)
                LDSM4(bh + 4*np, bb + 20480u + b_off + np * 1280u + ko);
#pragma unroll
            for (int mt = 0; mt < 4; mt++)
#pragma unroll
                for (int nt = 0; nt < 4; nt++)
                    MMA16816(acc[mt][nt], ah + 4*mt,
                             bh[(nt >> 1)*4 + (nt & 1)*2],
                             bh[(nt >> 1)*4 + (nt & 1)*2 + 1]);
#pragma unroll
            for (int np = 0; np < 2; np++)
                LDSM4(bl + 4*np, bb + 30720u + b_off + np * 1280u + ko);
#pragma unroll
            for (int mt = 0; mt < 4; mt++)
#pragma unroll
                for (int nt = 0; nt < 4; nt++)
                    MMA16816(acc[mt][nt], ah + 4*mt,
                             bl[(nt >> 1)*4 + (nt & 1)*2],
                             bl[(nt >> 1)*4 + (nt & 1)*2 + 1]);
#pragma unroll
            for (int mt = 0; mt < 4; mt++)
                LDSM4(al + 4*mt, bb + 10240u + a_off + mt * 1280u + ko);
#pragma unroll
            for (int mt = 0; mt < 4; mt++)
#pragma unroll
                for (int nt = 0; nt < 4; nt++)
                    MMA16816(acc[mt][nt], al + 4*mt,
                             bh[(nt >> 1)*4 + (nt & 1)*2],
                             bh[(nt >> 1)*4 + (nt & 1)*2 + 1]);
        }
    }

    // epilogue: acc[mt][nt] rows (l/4, l/4+8), cols 2*(l%4)+{0,1}
    const int r0 = l >> 2, c0 = (l & 3) * 2;
#pragma unroll
    for (int mt = 0; mt < 4; mt++) {
        const int row = m0 + wm*64 + mt*16 + r0;
#pragma unroll
        for (int nt = 0; nt < 4; nt++) {
            const int col = n0 + wn*32 + nt*8 + c0;
            float b0v = 0.f, b1v = 0.f;
            if (bias) { b0v = bias[col]; b1v = bias[col + 1]; }
            float v00 = acc[mt][nt][0] + b0v;
            float v01 = acc[mt][nt][1] + b1v;
            float v10 = acc[mt][nt][2] + b0v;
            float v11 = acc[mt][nt][3] + b1v;
            if (act) {
                v00 = 1.f / (1.f + __expf(-v00));
                v01 = 1.f / (1.f + __expf(-v01));
                v10 = 1.f / (1.f + __expf(-v10));
                v11 = 1.f / (1.f + __expf(-v11));
            }
            float2 p0; p0.x = v00; p0.y = v01;
            float2 p1; p1.x = v10; p1.y = v11;
            *(float2*)(C + (size_t)row * Nt + col)       = p0;
            *(float2*)(C + (size_t)(row + 8) * Nt + col) = p1;
        }
    }
}

// ---------------- beta = sigmoid(x @ Wb^T + bb), Wb: (8,1024) ---------------
__global__ __launch_bounds__(256) void beta_proj(
    const float* __restrict__ x, const float* __restrict__ Wb,
    const float* __restrict__ bb, float* __restrict__ Bt)
{
    const int m = blockIdx.x;
    const int w = threadIdx.x >> 5;
    const int lane = threadIdx.x & 31;
    const float* xr = x  + (size_t)m * HIDD;
    const float* wr = Wb + (size_t)w * HIDD;
    float s = 0.f;
#pragma unroll
    for (int k = lane * 4; k < HIDD; k += 128) {
        float4 xv = *(const float4*)(xr + k);
        float4 wv = *(const float4*)(wr + k);
        s += xv.x*wv.x + xv.y*wv.y + xv.z*wv.z + xv.w*wv.w;
    }
#pragma unroll
    for (int o = 16; o; o >>= 1) s += __shfl_xor_sync(0xffffffffu, s, o);
    if (lane == 0) Bt[m*8 + w] = 1.f / (1.f + __expf(-(s + bb[w])));
}

// ---------------- depthwise causal conv (K=4) + silu (+scale) ---------------
__global__ __launch_bounds__(256) void conv_silu(
    const float* __restrict__ in, const float* __restrict__ w,
    const float* __restrict__ bias, float* __restrict__ outp,
    int C, float scale)
{
    const int idx = blockIdx.x * blockDim.x + threadIdx.x;
    if (idx >= MROWS * C) return;
    const int c = idx % C;
    const int m = idx / C;
    const int t = m & (TSEQ - 1);
    const float* wc = w + c * 4;
    float acc = bias[c];
#pragma unroll
    for (int j = 0; j < 4; j++) {
        const int tt = t - 3 + j;
        if (tt >= 0) acc = fmaf(wc[j], in[(size_t)(m - 3 + j) * C + c], acc);
    }
    const float s = acc * (1.f / (1.f + __expf(-acc)));
    outp[(size_t)m * C + c] = s * scale;
}

// ---------------- gated delta-rule recurrence -------------------------------
__global__ __launch_bounds__(64) void delta_recurrence(
    const float* __restrict__ Qc, const float* __restrict__ Kc,
    const float* __restrict__ Vc, const float* __restrict__ Ag,
    const float* __restrict__ Bt, float* __restrict__ O)
{
    const int bh = blockIdx.x;
    const int b = bh >> 3, h = bh & 7;
    const int tid = threadIdx.x;
    const int w   = tid >> 5;
    const int lane = tid & 31;
    const int hlf = tid & 1;
    const int vcol = blockIdx.y * 32 + (tid >> 1);

    __shared__ float sk[2][2][68];
    __shared__ float sq[2][2][68];

    float S[32];
#pragma unroll
    for (int i = 0; i < 32; i++) S[i] = 0.f;

    const float* kb = Kc + (size_t)b * TSEQ * 512  + h * 64;
    const float* qb = Qc + (size_t)b * TSEQ * 512  + h * 64;
    const float* vb = Vc + (size_t)b * TSEQ * 1024 + h * 128 + vcol;
    const float* ab = Ag + (size_t)b * TSEQ * 1024 + h * 128 + vcol;
    const float* bbp = Bt + (size_t)b * TSEQ * 8   + h;
    float*       ob = O  + (size_t)b * TSEQ * 1024 + h * 128 + vcol;

    const int e  = 2 * lane;
    const int p0 = e + (e >> 5);
    const int kpad = hlf * 33;

    float2 kn = *(const float2*)(kb + e);
    float2 qn = *(const float2*)(qb + e);
    float a_n = ab[0], v_n = vb[0], be_n = bbp[0];

    int buf = 1;
    for (int t = 0; t < TSEQ; t++) {
        buf ^= 1;
        sk[w][buf][p0]   = kn.x; sk[w][buf][p0+1] = kn.y;
        sq[w][buf][p0]   = qn.x; sq[w][buf][p0+1] = qn.y;
        const float a_c = a_n, v_c = v_n, be_c = be_n;
        __syncwarp();
        if (t + 1 < TSEQ) {
            const size_t r = (size_t)(t + 1);
            kn = *(const float2*)(kb + r * 512 + e);
            qn = *(const float2*)(qb + r * 512 + e);
            a_n = ab[r * 1024]; v_n = vb[r * 1024]; be_n = bbp[r * 8];
        }
        const float* skc = &sk[w][buf][kpad];
        const float* sqc = &sq[w][buf][kpad];

        float r0 = 0.f, r1 = 0.f;
#pragma unroll
        for (int j = 0; j < 32; j += 2) {
            r0 = fmaf(skc[j],   S[j],   r0);
            r1 = fmaf(skc[j+1], S[j+1], r1);
        }
        float rd = r0 + r1;
        rd += __shfl_xor_sync(0xffffffffu, rd, 1);
        const float cc = be_c * (rd - v_c);

        float o0 = 0.f, o1 = 0.f;
#pragma unroll
        for (int j = 0; j < 32; j += 2) {
            const float k0v = skc[j], k1v = skc[j+1];
            S[j]   = fmaf(a_c, S[j],   -cc * k0v);
            S[j+1] = fmaf(a_c, S[j+1], -cc * k1v);
            o0 = fmaf(sqc[j],   S[j],   o0);
            o1 = fmaf(sqc[j+1], S[j+1], o1);
        }
        float oo = o0 + o1;
        oo += __shfl_xor_sync(0xffffffffu, oo, 1);
        if (hlf == 0) ob[(size_t)t * 1024] = oo;
    }
}

// ---------------- LayerNorm over DV + sigmoid-gate multiply (in place) ------
__global__ __launch_bounds__(256) void ln_gate(
    float* __restrict__ O, const float* __restrict__ G,
    const float* __restrict__ lnw, const float* __restrict__ lnb)
{
    const int g = blockIdx.x * 8 + (threadIdx.x >> 5);
    const int lane = threadIdx.x & 31;
    const int m = g >> 3, h = g & 7;
    float* row = O + (size_t)m * 1024 + h * 128;
    const float* grow = G + (size_t)m * 1024 + h * 128;

    float xs[4];
    float sum = 0.f;
#pragma unroll
    for (int i = 0; i < 4; i++) { xs[i] = row[lane + 32*i]; sum += xs[i]; }
#pragma unroll
    for (int o = 16; o; o >>= 1) sum += __shfl_xor_sync(0xffffffffu, sum, o);
    const float mu = sum * (1.f / 128.f);

    float vs = 0.f;
#pragma unroll
    for (int i = 0; i < 4; i++) { const float d = xs[i] - mu; vs = fmaf(d, d, vs); }
#pragma unroll
    for (int o = 16; o; o >>= 1) vs += __shfl_xor_sync(0xffffffffu, vs, o);
    const float rstd = rsqrtf(vs * (1.f / 128.f) + 1e-5f);

#pragma unroll
    for (int i = 0; i < 4; i++) {
        const int c = lane + 32*i;
        row[c] = ((xs[i] - mu) * rstd * lnw[c] + lnb[c]) * grow[c];
    }
}

// ---------------- launch ----------------------------------------------------
extern "C" void kernel_launch(void* const* d_in, const int* in_sizes, int n_in,
                              void* d_out, int out_size)
{
    const float* x   = (const float*)d_in[0];
    const float* Wq  = (const float*)d_in[1];
    const float* Wk  = (const float*)d_in[2];
    const float* Wv  = (const float*)d_in[3];
    const float* Wa  = (const float*)d_in[4];
    const float* ba  = (const float*)d_in[5];
    const float* Wb  = (const float*)d_in[6];
    const float* bbv = (const float*)d_in[7];
    const float* Wg  = (const float*)d_in[8];
    const float* Wo  = (const float*)d_in[9];
    const float* qcw = (const float*)d_in[10];
    const float* qcb = (const float*)d_in[11];
    const float* kcw = (const float*)d_in[12];
    const float* kcb = (const float*)d_in[13];
    const float* vcw = (const float*)d_in[14];
    const float* vcb = (const float*)d_in[15];
    const float* lnw = (const float*)d_in[16];
    const float* lnb = (const float*)d_in[17];
    float* outp = (float*)d_out;

    float *Q, *K, *V, *Qc, *Kc, *Vc, *A, *G, *Bt, *O;
    __nv_bfloat16 *Xhi, *Xlo, *Ohi, *Olo, *Whi, *Wlo;
    cudaGetSymbolAddress((void**)&Q,  g_Q);
    cudaGetSymbolAddress((void**)&K,  g_K);
    cudaGetSymbolAddress((void**)&V,  g_V);
    cudaGetSymbolAddress((void**)&Qc, g_Qc);
    cudaGetSymbolAddress((void**)&Kc, g_Kc);
    cudaGetSymbolAddress((void**)&Vc, g_Vc);
    cudaGetSymbolAddress((void**)&A,  g_A);
    cudaGetSymbolAddress((void**)&G,  g_G);
    cudaGetSymbolAddress((void**)&Bt, g_Bt);
    cudaGetSymbolAddress((void**)&O,  g_O);
    cudaGetSymbolAddress((void**)&Xhi, g_Xhi);
    cudaGetSymbolAddress((void**)&Xlo, g_Xlo);
    cudaGetSymbolAddress((void**)&Ohi, g_Ohi);
    cudaGetSymbolAddress((void**)&Olo, g_Olo);
    cudaGetSymbolAddress((void**)&Whi, g_Whi);
    cudaGetSymbolAddress((void**)&Wlo, g_Wlo);

    cudaFuncSetAttribute(gemm_hmma, cudaFuncAttributeMaxDynamicSharedMemorySize, GSMEM);

    // bf16 splits: activations + all weights
    split_bf16<<<(MROWS*1024/4 + 255)/256, 256>>>(x, Xhi, Xlo, MROWS*1024/4);
    split_bf16<<<(524288/4 + 255)/256, 256>>>(Wq, Whi + WOFF_Q, Wlo + WOFF_Q, 524288/4);
    split_bf16<<<(524288/4 + 255)/256, 256>>>(Wk, Whi + WOFF_K, Wlo + WOFF_K, 524288/4);
    split_bf16<<<(1048576/4 + 255)/256, 256>>>(Wv, Whi + WOFF_V, Wlo + WOFF_V, 1048576/4);
    split_bf16<<<(1048576/4 + 255)/256, 256>>>(Wa, Whi + WOFF_A, Wlo + WOFF_A, 1048576/4);
    split_bf16<<<(1048576/4 + 255)/256, 256>>>(Wg, Whi + WOFF_G, Wlo + WOFF_G, 1048576/4);
    split_bf16<<<(1048576/4 + 255)/256, 256>>>(Wo, Whi + WOFF_O, Wlo + WOFF_O, 1048576/4);

    // input projections on HMMA tensor path
    gemm_hmma<<<dim3(4, 64), 256, GSMEM>>>(Xhi, Xlo, Whi + WOFF_Q, Wlo + WOFF_Q, nullptr, Q, 512, 0);
    gemm_hmma<<<dim3(4, 64), 256, GSMEM>>>(Xhi, Xlo, Whi + WOFF_K, Wlo + WOFF_K, nullptr, K, 512, 0);
    gemm_hmma<<<dim3(8, 64), 256, GSMEM>>>(Xhi, Xlo, Whi + WOFF_V, Wlo + WOFF_V, nullptr, V, 1024, 0);
    gemm_hmma<<<dim3(8, 64), 256, GSMEM>>>(Xhi, Xlo, Whi + WOFF_A, Wlo + WOFF_A, ba,      A, 1024, 1);
    gemm_hmma<<<dim3(8, 64), 256, GSMEM>>>(Xhi, Xlo, Whi + WOFF_G, Wlo + WOFF_G, nullptr, G, 1024, 1);
    beta_proj<<<MROWS, 256>>>(x, Wb, bbv, Bt);

    // depthwise causal conv + silu (k gets the DK^-0.5 scale fused)
    conv_silu<<<(MROWS*512 +255)/256, 256>>>(Q, qcw, qcb, Qc,  512, 1.f);
    conv_silu<<<(MROWS*512 +255)/256, 256>>>(K, kcw, kcb, Kc,  512, 0.125f);
    conv_silu<<<(MROWS*1024+255)/256, 256>>>(V, vcw, vcb, Vc, 1024, 1.f);

    // sequential gated delta-rule scan
    delta_recurrence<<<dim3(NB*NH, 4), 64>>>(Qc, Kc, Vc, A, Bt, O);

    // LN + gate, split, then output projection
    ln_gate<<<MROWS, 256>>>(O, G, lnw, lnb);
    split_bf16<<<(MROWS*1024/4 + 255)/256, 256>>>(O, Ohi, Olo, MROWS*1024/4);
    gemm_hmma<<<dim3(8, 64), 256, GSMEM>>>(Ohi, Olo, Whi + WOFF_O, Wlo + WOFF_O, nullptr, outp, 1024, 0);
}